// round 1
// baseline (speedup 1.0000x reference)
#include <cuda_runtime.h>
#include <math.h>

#define NI   3
#define NS   32
#define NC   512
#define HH   22
#define OH   23
#define NPIX (OH*OH)        // 529
#define HW   (HH*HH)        // 484
#define NE   (NI*NS)        // 96
#define TAPS 16
#define WSZ  (NS*NC*TAPS)   // 262144
#define CSPLIT 8
#define CPB  (NC/CSPLIT)    // 64 channels per conv block
#define PH   27             // padded tile stride (conv feat + grad rm)

// ---------------- scratch (device globals; no runtime allocation) ----------------
__device__ float g_spart[CSPLIT*NE*NPIX]; // conv partials per channel-chunk
__device__ float g_label[NE*NPIX];
__device__ float g_rm[NE*NPIX];           // residuals_mapped
__device__ float g_w[WSZ];                // working weights
__device__ float g_wg[WSZ];               // weights_grad
__device__ float g_alpha_num[NS];
__device__ float g_alpha_den[NS];
__device__ float g_loss_data[8];
__device__ float g_wsq[8];

// ---------------- helpers ----------------
__device__ __forceinline__ float block_reduce_sum(float v, float* sbuf) {
    int lane = threadIdx.x & 31, wid = threadIdx.x >> 5;
    #pragma unroll
    for (int o = 16; o > 0; o >>= 1) v += __shfl_down_sync(0xffffffffu, v, o);
    if (lane == 0) sbuf[wid] = v;
    __syncthreads();
    int nw = (blockDim.x + 31) >> 5;
    v = (threadIdx.x < nw) ? sbuf[threadIdx.x] : 0.f;
    if (wid == 0) {
        #pragma unroll
        for (int o = 16; o > 0; o >>= 1) v += __shfl_down_sync(0xffffffffu, v, o);
    }
    return v;  // valid on thread 0
}

// ---------------- init: copy weights, build label, zero accumulators ----------------
__global__ void k_init(const float* __restrict__ w_in, const float* __restrict__ bb) {
    int idx = blockIdx.x * 256 + threadIdx.x;
    if (idx < WSZ) g_w[idx] = w_in[idx];
    if (idx < NE*NPIX) {
        int e = idx / NPIX, p = idx - e*NPIX;
        int y = p / OH, x = p - y*OH;
        const float* b = bb + e*4;
        float cc = (b[0] + 0.5f*b[2]) * 0.0625f;   // col center
        float cr = (b[1] + 0.5f*b[3]) * 0.0625f;   // row center
        float dy = (float)y - cr, dx = (float)x - cc;
        g_label[idx] = expf(-0.5f*dy*dy) * expf(-0.5f*dx*dx);
    }
    if (blockIdx.x == 0 && threadIdx.x < 8) {
        g_loss_data[threadIdx.x] = 0.f;
        g_wsq[threadIdx.x] = 0.f;
    }
}

// ---------------- conv: scores partials, one (i,s) x 64-channel slab per block ----------------
// out[e][y][x] partial = sum_{c in chunk} sum_{ky,kx} feat[e,c,y+ky-2,x+kx-2] * w[s,c,ky,kx]
__global__ __launch_bounds__(96) void k_conv(const float* __restrict__ feat, int use_wg) {
    __shared__ float sf[8*PH*PH];   // 8 channels, zero-padded 27x27
    __shared__ float swt[128];      // 8 channels x 16 taps
    const float* wts = use_wg ? g_wg : g_w;

    int b = blockIdx.x;
    int e = b % NE;              // i*NS + s
    int chunk = b / NE;          // 0..7
    int s = e % NS;
    int tid = threadIdx.x;
    int row = tid >> 2;          // 0..23 (row 23 idle)
    int xo  = (tid & 3) * 6;     // 0,6,12,18

    for (int k = tid; k < 8*PH*PH; k += 96) sf[k] = 0.f;

    float a0=0.f,a1=0.f,a2=0.f,a3=0.f,a4=0.f,a5=0.f;
    const float* fbase = feat + ((size_t)e*NC + (size_t)chunk*CPB)*HW;
    const float* wbase = wts + (s*NC + chunk*CPB)*TAPS;

    #pragma unroll 1
    for (int cc0 = 0; cc0 < CPB; cc0 += 8) {
        __syncthreads();
        for (int k = tid; k < 8*HW; k += 96) {
            int ch = k / HW, q = k - ch*HW;
            int u = q / HH, v = q - u*HH;
            sf[ch*(PH*PH) + (u+2)*PH + (v+2)] = fbase[cc0*HW + k];
        }
        for (int k = tid; k < 128; k += 96) swt[k] = wbase[cc0*TAPS + k];
        __syncthreads();
        if (row < OH) {
            #pragma unroll
            for (int ch = 0; ch < 8; ch++) {
                const float4* w4 = reinterpret_cast<const float4*>(swt + ch*16);
                float4 wk0 = w4[0], wk1 = w4[1], wk2 = w4[2], wk3 = w4[3];
                const float* sfc = sf + ch*(PH*PH);
                #pragma unroll
                for (int ky = 0; ky < 4; ky++) {
                    float4 wv = (ky==0) ? wk0 : (ky==1) ? wk1 : (ky==2) ? wk2 : wk3;
                    const float* fr = sfc + (row+ky)*PH + xo;
                    float f0=fr[0],f1=fr[1],f2=fr[2],f3=fr[3],f4=fr[4],
                          f5=fr[5],f6=fr[6],f7=fr[7],f8=fr[8];
                    a0=fmaf(f0,wv.x,a0); a0=fmaf(f1,wv.y,a0); a0=fmaf(f2,wv.z,a0); a0=fmaf(f3,wv.w,a0);
                    a1=fmaf(f1,wv.x,a1); a1=fmaf(f2,wv.y,a1); a1=fmaf(f3,wv.z,a1); a1=fmaf(f4,wv.w,a1);
                    a2=fmaf(f2,wv.x,a2); a2=fmaf(f3,wv.y,a2); a2=fmaf(f4,wv.z,a2); a2=fmaf(f5,wv.w,a2);
                    a3=fmaf(f3,wv.x,a3); a3=fmaf(f4,wv.y,a3); a3=fmaf(f5,wv.z,a3); a3=fmaf(f6,wv.w,a3);
                    a4=fmaf(f4,wv.x,a4); a4=fmaf(f5,wv.y,a4); a4=fmaf(f6,wv.z,a4); a4=fmaf(f7,wv.w,a4);
                    a5=fmaf(f5,wv.x,a5); a5=fmaf(f6,wv.y,a5); a5=fmaf(f7,wv.z,a5); a5=fmaf(f8,wv.w,a5);
                }
            }
        }
    }
    if (row < OH) {
        float* op = g_spart + ((size_t)chunk*NE + e)*NPIX + row*OH;
        float av[6] = {a0,a1,a2,a3,a4,a5};
        #pragma unroll
        for (int j = 0; j < 6; j++) if (xo + j < OH) op[xo + j] = av[j];
    }
}

// ---------------- residuals + loss_data[t], zero per-iter alpha accumulators ----------------
__global__ void k_resid(int t) {
    __shared__ float sred[32];
    int idx = blockIdx.x * 256 + threadIdx.x;
    float term = 0.f;
    if (idx < NE*NPIX) {
        float ssum = 0.f;
        #pragma unroll
        for (int ch = 0; ch < CSPLIT; ch++) ssum += g_spart[ch*(NE*NPIX) + idx];
        float d = ssum - g_label[idx];
        g_rm[idx] = d * (1.f/3.f);
        term = d * d * (1.f/3.f);
    }
    float tot = block_reduce_sum(term, sred);
    if (threadIdx.x == 0) atomicAdd(&g_loss_data[t], tot);
    if (blockIdx.x == 0 && threadIdx.x < NS) {
        g_alpha_num[threadIdx.x] = 0.f;
        g_alpha_den[threadIdx.x] = 0.f;
    }
}

// ---------------- grad: wg = corr(feat, rm) + reg*w; alpha_num; wsq ----------------
// block = (s, 16-channel group), 64 threads = 16 channels x 4 ky
__global__ __launch_bounds__(64) void k_grad(const float* __restrict__ feat,
                                             const float* __restrict__ freg, int t) {
    __shared__ float sfeat[16*HW];      // 7744 floats
    __shared__ float srm[3*PH*PH];      // padded rm, all 3 images
    __shared__ float sred[32];

    int s  = blockIdx.x >> 5;           // /32
    int cg = blockIdx.x & 31;
    int c0 = cg * 16;
    int tid = threadIdx.x;
    int cl = tid >> 2;                  // 0..15 channel within group
    int ky = tid & 3;

    for (int k = tid; k < 3*PH*PH; k += 64) srm[k] = 0.f;
    __syncthreads();
    for (int k = tid; k < 3*NPIX; k += 64) {
        int i = k / NPIX, p = k - i*NPIX;
        int y = p / OH, x = p - y*OH;
        srm[i*(PH*PH) + (y+2)*PH + (x+2)] = g_rm[(i*NS + s)*NPIX + p];
    }

    float acc0=0.f, acc1=0.f, acc2=0.f, acc3=0.f;
    for (int i = 0; i < NI; i++) {
        __syncthreads();
        const float* fsrc = feat + (((size_t)i*NS + s)*NC + c0)*HW;
        for (int k = tid; k < 16*HW; k += 64) sfeat[k] = fsrc[k];
        __syncthreads();
        const float* fch = sfeat + cl*HW;
        const float* rb  = srm + i*(PH*PH);
        #pragma unroll 1
        for (int u = 0; u < HH; u++) {
            const float* fr  = fch + u*HH;
            const float* rmr = rb + (u + 4 - ky)*PH;
            float r0 = rmr[1], r1 = rmr[2], r2 = rmr[3];
            #pragma unroll
            for (int v = 0; v < HH; v++) {
                float r3 = rmr[v+4];
                float f  = fr[v];
                acc3 = fmaf(f, r0, acc3);   // kx=3 -> col v+1
                acc2 = fmaf(f, r1, acc2);
                acc1 = fmaf(f, r2, acc1);
                acc0 = fmaf(f, r3, acc0);   // kx=0 -> col v+4
                r0 = r1; r1 = r2; r2 = r3;
            }
        }
    }

    float fr0 = freg[0];
    float regv = fmaxf(fr0*fr0, 1e-6f);
    int base = (s*NC + c0 + cl)*TAPS + ky*4;
    float accs[4] = {acc0, acc1, acc2, acc3};
    float nsum = 0.f, wsum = 0.f;
    #pragma unroll
    for (int kx = 0; kx < 4; kx++) {
        float wv = g_w[base + kx];
        float wg = accs[kx] + regv*wv;
        g_wg[base + kx] = wg;
        nsum += wg*wg;
        wsum += wv*wv;
    }
    __syncthreads();
    float tn = block_reduce_sum(nsum, sred);
    if (tid == 0) atomicAdd(&g_alpha_num[s], tn);
    __syncthreads();
    float tw = block_reduce_sum(wsum, sred);
    if (tid == 0) atomicAdd(&g_wsq[t], tw);
}

// ---------------- alpha_den: (1/3) * sum over (i,y,x) of conv(feat,wg)^2 ----------------
__global__ void k_den() {
    __shared__ float sred[32];
    int e = blockIdx.x;
    int s = e % NS;
    float sum = 0.f;
    for (int p = threadIdx.x; p < NPIX; p += 256) {
        float v = 0.f;
        #pragma unroll
        for (int ch = 0; ch < CSPLIT; ch++) v += g_spart[ch*(NE*NPIX) + e*NPIX + p];
        sum += v*v;
    }
    float tot = block_reduce_sum(sum, sred);
    if (threadIdx.x == 0) atomicAdd(&g_alpha_den[s], tot * (1.f/3.f));
}

// ---------------- weight update ----------------
__global__ void k_update(const float* __restrict__ lsl, const float* __restrict__ freg) {
    int idx = blockIdx.x * 256 + threadIdx.x;   // grid sized exactly WSZ
    int s = idx >> 13;                          // / 8192
    float fr0 = freg[0];
    float regv = fmaxf(fr0*fr0, 1e-6f);
    float num = g_alpha_num[s];
    float den = fmaxf(g_alpha_den[s] + regv*num, 1e-8f);
    float alpha = num / den;
    float step = expf(lsl[0]);
    g_w[idx] -= step * alpha * g_wg[idx];
}

// ---------------- final loss pieces + weight writeback ----------------
__global__ void k_final(float* __restrict__ out) {
    __shared__ float sred[32];
    int b = blockIdx.x;
    if (b < NE) {
        float sum = 0.f;
        for (int p = threadIdx.x; p < NPIX; p += 256) {
            float v = 0.f;
            #pragma unroll
            for (int ch = 0; ch < CSPLIT; ch++) v += g_spart[ch*(NE*NPIX) + b*NPIX + p];
            float d = v - g_label[b*NPIX + p];
            sum += d*d;
        }
        float tot = block_reduce_sum(sum, sred);
        if (threadIdx.x == 0) atomicAdd(&g_loss_data[5], tot * (1.f/3.f));
    } else {
        int j = (b - NE) * 256 + threadIdx.x;   // covers exactly WSZ
        float wv = g_w[j];
        out[j] = wv;
        float tot = block_reduce_sum(wv*wv, sred);
        if (threadIdx.x == 0) atomicAdd(&g_wsq[5], tot);
    }
}

// ---------------- losses writeback ----------------
__global__ void k_last(float* __restrict__ out, const float* __restrict__ freg) {
    float fr0 = freg[0];
    float regv = fmaxf(fr0*fr0, 1e-6f);
    int t = threadIdx.x;
    if (t < 6) out[WSZ + t] = (g_loss_data[t] + regv * g_wsq[t]) * (1.f/(float)NS);
}

// ---------------- launcher ----------------
extern "C" void kernel_launch(void* const* d_in, const int* in_sizes, int n_in,
                              void* d_out, int out_size) {
    const float* w_in = (const float*)d_in[0];
    const float* feat = (const float*)d_in[1];
    const float* bb   = (const float*)d_in[2];
    const float* lsl  = (const float*)d_in[3];
    const float* freg = (const float*)d_in[4];
    float* out = (float*)d_out;
    (void)in_sizes; (void)n_in; (void)out_size;

    k_init<<<1024, 256>>>(w_in, bb);
    for (int t = 0; t < 5; t++) {
        k_conv<<<NE*CSPLIT, 96>>>(feat, 0);                 // scores partials
        k_resid<<<(NE*NPIX + 255)/256, 256>>>(t);           // rm + loss_data[t]
        k_grad<<<NS*32, 64>>>(feat, freg, t);               // wg, alpha_num, wsq[t]
        k_conv<<<NE*CSPLIT, 96>>>(feat, 1);                 // scores_grad partials
        k_den<<<NE, 256>>>();                               // alpha_den
        k_update<<<WSZ/256, 256>>>(lsl, freg);              // w -= step*alpha*wg
    }
    k_conv<<<NE*CSPLIT, 96>>>(feat, 0);                     // final scores
    k_final<<<NE + WSZ/256, 256>>>(out);                    // loss_data[5], wsq[5], weights out
    k_last<<<1, 32>>>(out, freg);                           // losses out
}

// round 2
// speedup vs baseline: 1.6723x; 1.6723x over previous
#include <cuda_runtime.h>
#include <math.h>

#define NI   3
#define NS   32
#define NC   512
#define HH   22
#define OH   23
#define NPIX (OH*OH)        // 529
#define HW   (HH*HH)        // 484
#define NE   (NI*NS)        // 96
#define TAPS 16
#define WSZ  (NS*NC*TAPS)   // 262144
#define CSPLIT 16
#define CPB  (NC/CSPLIT)    // 32 channels per conv block
#define PH   27             // padded tile stride (conv feat + rm)
#define SPP  4              // channel-pairs staged per conv stage
#define GPAIRS 8            // channel-pairs staged per grad stage
#define GFW  24             // grad feat smem row stride (22 + 2 zero pad)

// ---------------- scratch (device globals; no runtime allocation) ----------------
__device__ float g_spart[CSPLIT*NE*NPIX]; // conv partials per channel-chunk
__device__ float g_label[NE*NPIX];
__device__ float g_rm[NE*NPIX];           // residuals_mapped
__device__ float g_w[WSZ];                // working weights
__device__ float g_wg[WSZ];               // weights_grad
__device__ float g_wgpart[NI*WSZ];        // per-image grad partials
__device__ float g_alpha_num[NS];
__device__ float g_alpha_den[NS];
__device__ float g_loss_data[8];
__device__ float g_wsq[8];

// ---------------- helpers ----------------
__device__ __forceinline__ float2 f2fma(float2 a, float2 b, float2 c) {
    float2 d;
    asm("fma.rn.f32x2 %0, %1, %2, %3;"
        : "=l"(reinterpret_cast<unsigned long long&>(d))
        : "l"(reinterpret_cast<unsigned long long&>(a)),
          "l"(reinterpret_cast<unsigned long long&>(b)),
          "l"(reinterpret_cast<unsigned long long&>(c)));
    return d;
}

__device__ __forceinline__ float block_reduce_sum(float v, float* sbuf) {
    int lane = threadIdx.x & 31, wid = threadIdx.x >> 5;
    #pragma unroll
    for (int o = 16; o > 0; o >>= 1) v += __shfl_down_sync(0xffffffffu, v, o);
    if (lane == 0) sbuf[wid] = v;
    __syncthreads();
    int nw = (blockDim.x + 31) >> 5;
    v = (threadIdx.x < nw) ? sbuf[threadIdx.x] : 0.f;
    if (wid == 0) {
        #pragma unroll
        for (int o = 16; o > 0; o >>= 1) v += __shfl_down_sync(0xffffffffu, v, o);
    }
    return v;  // valid on thread 0
}

// ---------------- init: copy weights, build label, zero accumulators ----------------
__global__ void k_init(const float* __restrict__ w_in, const float* __restrict__ bb) {
    int idx = blockIdx.x * 256 + threadIdx.x;
    if (idx < WSZ) g_w[idx] = w_in[idx];
    if (idx < NE*NPIX) {
        int e = idx / NPIX, p = idx - e*NPIX;
        int y = p / OH, x = p - y*OH;
        const float* b = bb + e*4;
        float cc = (b[0] + 0.5f*b[2]) * 0.0625f;   // col center
        float cr = (b[1] + 0.5f*b[3]) * 0.0625f;   // row center
        float dy = (float)y - cr, dx = (float)x - cc;
        g_label[idx] = expf(-0.5f*dy*dy) * expf(-0.5f*dx*dx);
    }
    if (blockIdx.x == 0 && threadIdx.x < 8) {
        g_loss_data[threadIdx.x] = 0.f;
        g_wsq[threadIdx.x] = 0.f;
    }
}

// ---------------- conv: one (e, 32-channel chunk) per block ----------------
// 96 threads = 24 output tiles (4x across, 6y down; tile = 6 wide x 4 tall) x 4 pair-lanes.
// Channel pairs interleaved in smem as float2; packed fma.rn.f32x2 throughout.
__global__ __launch_bounds__(96, 6) void k_conv(const float* __restrict__ feat, int use_wg) {
    __shared__ float2 sf[SPP][PH*PH];   // 4 pairs, zero-padded 27x27, 2-ch interleaved
    __shared__ float2 sw[SPP][TAPS];    // taps, 2-ch interleaved
    const float* wts = use_wg ? g_wg : g_w;

    int b = blockIdx.x;
    int e = b % NE;              // i*NS + s
    int chunk = b / NE;          // 0..15
    int s = e % NS;
    int tid = threadIdx.x;
    int pl = tid & 3;            // pair lane
    int t  = tid >> 2;           // tile 0..23
    int tx = t & 3, ty = t >> 2; // tx 0..3, ty 0..5
    int x0 = tx * 6, y0 = ty * 4;

    // zero-pad entire stage buffers once (interiors are overwritten every stage)
    for (int k = tid; k < SPP*PH*PH; k += 96) ((float2*)sf)[k] = make_float2(0.f, 0.f);

    float2 acc[4][6];
    #pragma unroll
    for (int r = 0; r < 4; r++)
        #pragma unroll
        for (int j = 0; j < 6; j++) acc[r][j] = make_float2(0.f, 0.f);

    const float* fbase = feat + ((size_t)e*NC + (size_t)chunk*CPB)*HW;
    const float* wbase = wts + (s*NC + chunk*CPB)*TAPS;

    #pragma unroll 1
    for (int st = 0; st < 4; st++) {
        __syncthreads();
        for (int k = tid; k < SPP*HW; k += 96) {
            int p = k / HW, q = k - p*HW;
            int u = q / HH, v = q - u*HH;
            int c0 = (st*SPP + p)*2;
            float2 val;
            val.x = fbase[(size_t)c0*HW + q];
            val.y = fbase[(size_t)(c0+1)*HW + q];
            sf[p][(u+2)*PH + (v+2)] = val;
        }
        for (int k = tid; k < SPP*TAPS; k += 96) {
            int p = k / TAPS, tap = k - p*TAPS;
            int c0 = (st*SPP + p)*2;
            sw[p][tap] = make_float2(wbase[(c0+0)*TAPS + tap], wbase[(c0+1)*TAPS + tap]);
        }
        __syncthreads();

        const float2* sfp = sf[pl];
        const float2* wv  = sw[pl];   // wv[ky*4+kx]
        #pragma unroll
        for (int su = 0; su < 7; su++) {
            const float2* fr = sfp + (y0+su)*PH + x0;
            float2 f[9];
            #pragma unroll
            for (int j = 0; j < 9; j++) f[j] = fr[j];
            #pragma unroll
            for (int ky = 0; ky < 4; ky++) {
                int r = su - ky;
                if (r < 0 || r > 3) continue;
                #pragma unroll
                for (int kx = 0; kx < 4; kx++) {
                    float2 w2 = wv[ky*4 + kx];
                    #pragma unroll
                    for (int j = 0; j < 6; j++)
                        acc[r][j] = f2fma(f[j+kx], w2, acc[r][j]);
                }
            }
        }
    }

    // sum 2 channels, reduce 4 pair-lanes via shfl (lanes pl = tid&3, groups aligned)
    float* op = g_spart + ((size_t)chunk*NE + e)*NPIX;
    #pragma unroll
    for (int r = 0; r < 4; r++) {
        #pragma unroll
        for (int j = 0; j < 6; j++) {
            float v = acc[r][j].x + acc[r][j].y;
            v += __shfl_down_sync(0xffffffffu, v, 1);
            v += __shfl_down_sync(0xffffffffu, v, 2);
            if (pl == 0) {
                int yy = y0 + r, xx = x0 + j;
                if (yy < OH && xx < OH) op[yy*OH + xx] = v;
            }
        }
    }
}

// ---------------- residuals + loss_data[t], zero per-iter alpha accumulators ----------------
__global__ void k_resid(int t) {
    __shared__ float sred[32];
    int idx = blockIdx.x * 256 + threadIdx.x;
    float term = 0.f;
    if (idx < NE*NPIX) {
        float ssum = 0.f;
        #pragma unroll
        for (int ch = 0; ch < CSPLIT; ch++) ssum += g_spart[ch*(NE*NPIX) + idx];
        float d = ssum - g_label[idx];
        g_rm[idx] = d * (1.f/3.f);
        term = d * d * (1.f/3.f);
    }
    float tot = block_reduce_sum(term, sred);
    if (threadIdx.x == 0) atomicAdd(&g_loss_data[t], tot);
    if (blockIdx.x == 0 && threadIdx.x < NS) {
        g_alpha_num[threadIdx.x] = 0.f;
        g_alpha_den[threadIdx.x] = 0.f;
    }
}

// ---------------- grad: per-image partial of corr(feat, rm) ----------------
// block = (i, s, 64-channel group). 128 threads = 8 pairs x 4 ky x 4 v-quarters
// per stage; 4 stages cover 32 pairs. Channel pairs packed as float2.
__global__ __launch_bounds__(128, 6) void k_grad(const float* __restrict__ feat) {
    __shared__ float2 sfeat[GPAIRS*HH*GFW/2 + GPAIRS*HH*GFW/2]; // 8 pairs x 22 rows x 24 (zero-padded cols)
    __shared__ float srm[PH*PH];                                 // padded rm for this image

    int b = blockIdx.x;
    int i = b / (NS*8);
    int rem = b - i*(NS*8);
    int s = rem >> 3;
    int cg = rem & 7;            // 64-channel group
    int tid = threadIdx.x;
    int vq = tid & 3;
    int ky = (tid >> 2) & 3;
    int pr = tid >> 4;           // 0..7 pair within stage
    int v0 = vq * 6;             // 0,6,12,18 ; uniform length 6 (cols 22,23 zero pad)

    // zero feat buffer once (cols 22,23 stay 0 forever), zero rm padding
    for (int k = tid; k < GPAIRS*HH*GFW; k += 128)
        ((float2*)sfeat)[k] = make_float2(0.f, 0.f);
    for (int k = tid; k < PH*PH; k += 128) srm[k] = 0.f;
    __syncthreads();
    for (int k = tid; k < NPIX; k += 128) {
        int y = k / OH, x = k - y*OH;
        srm[(y+2)*PH + (x+2)] = g_rm[(i*NS + s)*NPIX + k];
    }

    const float* fbase = feat + (((size_t)i*NS + s)*NC + cg*64)*HW;

    #pragma unroll 1
    for (int st = 0; st < 4; st++) {
        __syncthreads();
        for (int k = tid; k < GPAIRS*HW; k += 128) {
            int p = k / HW, q = k - p*HW;
            int u = q / HH, v = q - u*HH;
            int c0 = (st*GPAIRS + p)*2;
            float2 val;
            val.x = fbase[(size_t)c0*HW + q];
            val.y = fbase[(size_t)(c0+1)*HW + q];
            sfeat[p*(HH*GFW) + u*GFW + v] = val;
        }
        __syncthreads();

        float2 acc[4];
        #pragma unroll
        for (int kx = 0; kx < 4; kx++) acc[kx] = make_float2(0.f, 0.f);

        const float2* fch = sfeat + pr*(HH*GFW);
        #pragma unroll 1
        for (int u = 0; u < HH; u++) {
            const float* rmr = srm + (u + 4 - ky)*PH;
            float2 p0 = make_float2(rmr[v0+1], rmr[v0+1]);
            float2 p1 = make_float2(rmr[v0+2], rmr[v0+2]);
            float2 p2 = make_float2(rmr[v0+3], rmr[v0+3]);
            const float2* fr = fch + u*GFW + v0;
            #pragma unroll
            for (int v = 0; v < 6; v++) {
                float rnew = rmr[v0 + v + 4];
                float2 p3 = make_float2(rnew, rnew);
                float2 f = fr[v];
                acc[3] = f2fma(f, p0, acc[3]);
                acc[2] = f2fma(f, p1, acc[2]);
                acc[1] = f2fma(f, p2, acc[1]);
                acc[0] = f2fma(f, p3, acc[0]);
                p0 = p1; p1 = p2; p2 = p3;
            }
        }

        // reduce over the 4 v-quarters (lanes vq = tid&3, groups aligned)
        #pragma unroll
        for (int kx = 0; kx < 4; kx++) {
            acc[kx].x += __shfl_down_sync(0xffffffffu, acc[kx].x, 1);
            acc[kx].y += __shfl_down_sync(0xffffffffu, acc[kx].y, 1);
            acc[kx].x += __shfl_down_sync(0xffffffffu, acc[kx].x, 2);
            acc[kx].y += __shfl_down_sync(0xffffffffu, acc[kx].y, 2);
        }
        if (vq == 0) {
            int c = cg*64 + (st*GPAIRS + pr)*2;
            size_t base = (size_t)i*WSZ + (size_t)(s*NC + c)*TAPS + ky*4;
            #pragma unroll
            for (int kx = 0; kx < 4; kx++) {
                g_wgpart[base + kx]        = acc[kx].x;
                g_wgpart[base + TAPS + kx] = acc[kx].y;
            }
        }
    }
}

// ---------------- combine grad partials: wg = sum_i part + reg*w; alpha_num; wsq ----------------
__global__ void k_comb(const float* __restrict__ freg, int t) {
    __shared__ float sred[32];
    int idx = blockIdx.x * 256 + threadIdx.x;   // grid covers exactly WSZ
    int s = idx >> 13;                          // / 8192 (256 | 8192 so block is single-s)
    float fr0 = freg[0];
    float regv = fmaxf(fr0*fr0, 1e-6f);
    float w = g_w[idx];
    float wg = g_wgpart[idx] + g_wgpart[WSZ + idx] + g_wgpart[2*WSZ + idx] + regv*w;
    g_wg[idx] = wg;
    float tn = block_reduce_sum(wg*wg, sred);
    if (threadIdx.x == 0) atomicAdd(&g_alpha_num[s], tn);
    __syncthreads();
    float tw = block_reduce_sum(w*w, sred);
    if (threadIdx.x == 0) atomicAdd(&g_wsq[t], tw);
}

// ---------------- alpha_den: (1/3) * sum over (i,y,x) of conv(feat,wg)^2 ----------------
__global__ void k_den() {
    __shared__ float sred[32];
    int e = blockIdx.x;
    int s = e % NS;
    float sum = 0.f;
    for (int p = threadIdx.x; p < NPIX; p += 256) {
        float v = 0.f;
        #pragma unroll
        for (int ch = 0; ch < CSPLIT; ch++) v += g_spart[ch*(NE*NPIX) + e*NPIX + p];
        sum += v*v;
    }
    float tot = block_reduce_sum(sum, sred);
    if (threadIdx.x == 0) atomicAdd(&g_alpha_den[s], tot * (1.f/3.f));
}

// ---------------- weight update ----------------
__global__ void k_update(const float* __restrict__ lsl, const float* __restrict__ freg) {
    int idx = blockIdx.x * 256 + threadIdx.x;   // grid sized exactly WSZ
    int s = idx >> 13;                          // / 8192
    float fr0 = freg[0];
    float regv = fmaxf(fr0*fr0, 1e-6f);
    float num = g_alpha_num[s];
    float den = fmaxf(g_alpha_den[s] + regv*num, 1e-8f);
    float alpha = num / den;
    float step = expf(lsl[0]);
    g_w[idx] -= step * alpha * g_wg[idx];
}

// ---------------- final loss pieces + weight writeback ----------------
__global__ void k_final(float* __restrict__ out) {
    __shared__ float sred[32];
    int b = blockIdx.x;
    if (b < NE) {
        float sum = 0.f;
        for (int p = threadIdx.x; p < NPIX; p += 256) {
            float v = 0.f;
            #pragma unroll
            for (int ch = 0; ch < CSPLIT; ch++) v += g_spart[ch*(NE*NPIX) + b*NPIX + p];
            float d = v - g_label[b*NPIX + p];
            sum += d*d;
        }
        float tot = block_reduce_sum(sum, sred);
        if (threadIdx.x == 0) atomicAdd(&g_loss_data[5], tot * (1.f/3.f));
    } else {
        int j = (b - NE) * 256 + threadIdx.x;   // covers exactly WSZ
        float wv = g_w[j];
        out[j] = wv;
        float tot = block_reduce_sum(wv*wv, sred);
        if (threadIdx.x == 0) atomicAdd(&g_wsq[5], tot);
    }
}

// ---------------- losses writeback ----------------
__global__ void k_last(float* __restrict__ out, const float* __restrict__ freg) {
    float fr0 = freg[0];
    float regv = fmaxf(fr0*fr0, 1e-6f);
    int t = threadIdx.x;
    if (t < 6) out[WSZ + t] = (g_loss_data[t] + regv * g_wsq[t]) * (1.f/(float)NS);
}

// ---------------- launcher ----------------
extern "C" void kernel_launch(void* const* d_in, const int* in_sizes, int n_in,
                              void* d_out, int out_size) {
    const float* w_in = (const float*)d_in[0];
    const float* feat = (const float*)d_in[1];
    const float* bb   = (const float*)d_in[2];
    const float* lsl  = (const float*)d_in[3];
    const float* freg = (const float*)d_in[4];
    float* out = (float*)d_out;
    (void)in_sizes; (void)n_in; (void)out_size;

    k_init<<<1024, 256>>>(w_in, bb);
    for (int t = 0; t < 5; t++) {
        k_conv<<<NE*CSPLIT, 96>>>(feat, 0);                 // scores partials
        k_resid<<<(NE*NPIX + 255)/256, 256>>>(t);           // rm + loss_data[t] (+zero alphas)
        k_grad<<<NI*NS*8, 128>>>(feat);                     // per-image grad partials
        k_comb<<<WSZ/256, 256>>>(freg, t);                  // wg, alpha_num, wsq[t]
        k_conv<<<NE*CSPLIT, 96>>>(feat, 1);                 // scores_grad partials
        k_den<<<NE, 256>>>();                               // alpha_den
        k_update<<<WSZ/256, 256>>>(lsl, freg);              // w -= step*alpha*wg
    }
    k_conv<<<NE*CSPLIT, 96>>>(feat, 0);                     // final scores
    k_final<<<NE + WSZ/256, 256>>>(out);                    // loss_data[5], wsq[5], weights out
    k_last<<<1, 32>>>(out, freg);                           // losses out
}

// round 3
// speedup vs baseline: 2.1601x; 1.2917x over previous
#include <cuda_runtime.h>
#include <math.h>

#define NI   3
#define NS   32
#define NC   512
#define HH   22
#define OH   23
#define NPIX (OH*OH)        // 529
#define HW   (HH*HH)        // 484
#define NE   (NI*NS)        // 96
#define TAPS 16
#define WSZ  (NS*NC*TAPS)   // 262144
#define CSPLIT 16
#define CPB  (NC/CSPLIT)    // 32 channels per conv block
#define PH   27             // padded tile stride (conv feat + rm)
#define SPP  4              // channel-pairs staged per conv stage
#define GPAIRS 4            // channel-pairs staged per grad stage
#define GFW  24             // grad feat smem row stride (22 + 2 zero pad)

// ---------------- scratch (device globals; no runtime allocation) ----------------
__device__ float g_spart[CSPLIT*NE*NPIX]; // conv partials per channel-chunk
__device__ float g_label[NE*NPIX];
__device__ float g_scores[NE*NPIX];       // maintained scores (recurrence)
__device__ float g_sg[NE*NPIX];           // conv(feat, wg) summed
__device__ float g_rm[NE*NPIX];           // residuals_mapped
__device__ float g_w[WSZ];                // working weights
__device__ float g_wg[WSZ];               // weights_grad
__device__ float g_wgpart[NI*WSZ];        // per-image grad partials
__device__ float g_alpha_num[NS];
__device__ float g_alpha_den[NS];
__device__ float g_loss_data[8];
__device__ float g_wsq[8];

// ---------------- helpers ----------------
__device__ __forceinline__ float2 f2fma(float2 a, float2 b, float2 c) {
    float2 d;
    asm("fma.rn.f32x2 %0, %1, %2, %3;"
        : "=l"(reinterpret_cast<unsigned long long&>(d))
        : "l"(reinterpret_cast<unsigned long long&>(a)),
          "l"(reinterpret_cast<unsigned long long&>(b)),
          "l"(reinterpret_cast<unsigned long long&>(c)));
    return d;
}

__device__ __forceinline__ float block_reduce_sum(float v, float* sbuf) {
    int lane = threadIdx.x & 31, wid = threadIdx.x >> 5;
    #pragma unroll
    for (int o = 16; o > 0; o >>= 1) v += __shfl_down_sync(0xffffffffu, v, o);
    if (lane == 0) sbuf[wid] = v;
    __syncthreads();
    int nw = (blockDim.x + 31) >> 5;
    v = (threadIdx.x < nw) ? sbuf[threadIdx.x] : 0.f;
    if (wid == 0) {
        #pragma unroll
        for (int o = 16; o > 0; o >>= 1) v += __shfl_down_sync(0xffffffffu, v, o);
    }
    return v;  // valid on thread 0
}

// ---------------- init: copy weights, build label, zero accumulators ----------------
__global__ void k_init(const float* __restrict__ w_in, const float* __restrict__ bb) {
    int idx = blockIdx.x * 256 + threadIdx.x;
    if (idx < WSZ) g_w[idx] = w_in[idx];
    if (idx < NE*NPIX) {
        int e = idx / NPIX, p = idx - e*NPIX;
        int y = p / OH, x = p - y*OH;
        const float* b = bb + e*4;
        float cc = (b[0] + 0.5f*b[2]) * 0.0625f;   // col center
        float cr = (b[1] + 0.5f*b[3]) * 0.0625f;   // row center
        float dy = (float)y - cr, dx = (float)x - cc;
        g_label[idx] = expf(-0.5f*dy*dy) * expf(-0.5f*dx*dx);
    }
    if (blockIdx.x == 0 && threadIdx.x < 8) {
        g_loss_data[threadIdx.x] = 0.f;
        g_wsq[threadIdx.x] = 0.f;
    }
}

// ---------------- conv: one (e, 32-channel chunk) per block ----------------
// 96 threads = 24 output tiles (4x across, 6y down; tile = 6 wide x 4 tall) x 4 pair-lanes.
// Channel pairs interleaved in smem as float2; packed fma.rn.f32x2 throughout.
__global__ __launch_bounds__(96, 6) void k_conv(const float* __restrict__ feat, int use_wg) {
    __shared__ float2 sf[SPP][PH*PH];   // 4 pairs, zero-padded 27x27, 2-ch interleaved
    __shared__ float2 sw[SPP][TAPS];    // taps, 2-ch interleaved
    const float* wts = use_wg ? g_wg : g_w;

    int b = blockIdx.x;
    int e = b % NE;              // i*NS + s
    int chunk = b / NE;          // 0..15
    int s = e % NS;
    int tid = threadIdx.x;
    int pl = tid & 3;            // pair lane
    int t  = tid >> 2;           // tile 0..23
    int tx = t & 3, ty = t >> 2; // tx 0..3, ty 0..5
    int x0 = tx * 6, y0 = ty * 4;

    // zero-pad entire stage buffers once (interiors are overwritten every stage)
    for (int k = tid; k < SPP*PH*PH; k += 96) ((float2*)sf)[k] = make_float2(0.f, 0.f);

    float2 acc[4][6];
    #pragma unroll
    for (int r = 0; r < 4; r++)
        #pragma unroll
        for (int j = 0; j < 6; j++) acc[r][j] = make_float2(0.f, 0.f);

    const float* fbase = feat + ((size_t)e*NC + (size_t)chunk*CPB)*HW;
    const float* wbase = wts + (s*NC + chunk*CPB)*TAPS;

    #pragma unroll 1
    for (int st = 0; st < 4; st++) {
        __syncthreads();
        for (int k = tid; k < SPP*HW; k += 96) {
            int p = k / HW, q = k - p*HW;
            int u = q / HH, v = q - u*HH;
            int c0 = (st*SPP + p)*2;
            float2 val;
            val.x = fbase[(size_t)c0*HW + q];
            val.y = fbase[(size_t)(c0+1)*HW + q];
            sf[p][(u+2)*PH + (v+2)] = val;
        }
        for (int k = tid; k < SPP*TAPS; k += 96) {
            int p = k / TAPS, tap = k - p*TAPS;
            int c0 = (st*SPP + p)*2;
            sw[p][tap] = make_float2(wbase[(c0+0)*TAPS + tap], wbase[(c0+1)*TAPS + tap]);
        }
        __syncthreads();

        const float2* sfp = sf[pl];
        const float2* wv  = sw[pl];   // wv[ky*4+kx]
        #pragma unroll
        for (int su = 0; su < 7; su++) {
            const float2* fr = sfp + (y0+su)*PH + x0;
            float2 f[9];
            #pragma unroll
            for (int j = 0; j < 9; j++) f[j] = fr[j];
            #pragma unroll
            for (int ky = 0; ky < 4; ky++) {
                int r = su - ky;
                if (r < 0 || r > 3) continue;
                #pragma unroll
                for (int kx = 0; kx < 4; kx++) {
                    float2 w2 = wv[ky*4 + kx];
                    #pragma unroll
                    for (int j = 0; j < 6; j++)
                        acc[r][j] = f2fma(f[j+kx], w2, acc[r][j]);
                }
            }
        }
    }

    // sum 2 channels, reduce 4 pair-lanes via shfl (lanes pl = tid&3, groups aligned)
    float* op = g_spart + ((size_t)chunk*NE + e)*NPIX;
    #pragma unroll
    for (int r = 0; r < 4; r++) {
        #pragma unroll
        for (int j = 0; j < 6; j++) {
            float v = acc[r][j].x + acc[r][j].y;
            v += __shfl_down_sync(0xffffffffu, v, 1);
            v += __shfl_down_sync(0xffffffffu, v, 2);
            if (pl == 0) {
                int yy = y0 + r, xx = x0 + j;
                if (yy < OH && xx < OH) op[yy*OH + xx] = v;
            }
        }
    }
}

// ---------------- residuals + loss_data[t], zero per-iter alpha accumulators ----------------
// from_part: iter 0 sums conv partials and materializes g_scores; later iters read g_scores.
__global__ void k_resid(int t, int from_part) {
    __shared__ float sred[32];
    int idx = blockIdx.x * 256 + threadIdx.x;
    float term = 0.f;
    if (idx < NE*NPIX) {
        float ssum;
        if (from_part) {
            ssum = 0.f;
            #pragma unroll
            for (int ch = 0; ch < CSPLIT; ch++) ssum += g_spart[ch*(NE*NPIX) + idx];
            g_scores[idx] = ssum;
        } else {
            ssum = g_scores[idx];
        }
        float d = ssum - g_label[idx];
        g_rm[idx] = d * (1.f/3.f);
        term = d * d * (1.f/3.f);
    }
    float tot = block_reduce_sum(term, sred);
    if (threadIdx.x == 0) atomicAdd(&g_loss_data[t], tot);
    if (blockIdx.x == 0 && threadIdx.x < NS) {
        g_alpha_num[threadIdx.x] = 0.f;
        g_alpha_den[threadIdx.x] = 0.f;
    }
}

// ---------------- grad: per-image partial of corr(feat, rm) ----------------
// block = (i, s, 32-channel group). 128 threads = 4 pairs x 4 ky x 8 v-segments
// per stage; 4 stages cover 16 pairs. Channel pairs packed as float2.
__global__ __launch_bounds__(128, 8) void k_grad(const float* __restrict__ feat) {
    __shared__ float2 sfeat[GPAIRS*HH*GFW];  // 4 pairs x 22 rows x 24 cols (2 zero-pad)
    __shared__ float srm[PH*PH];             // padded rm for this image

    int b = blockIdx.x;
    int i = b / (NS*16);
    int rem = b - i*(NS*16);
    int s = rem >> 4;
    int cg = rem & 15;           // 32-channel group
    int tid = threadIdx.x;
    int vseg = tid & 7;
    int ky = (tid >> 3) & 3;
    int pr = tid >> 5;           // 0..3 pair within stage
    int v0 = vseg * 3;           // 0..21 ; uniform length 3 (cols 22,23 zero pad)

    // zero feat buffer once (cols 22,23 stay 0 forever), zero rm padding
    for (int k = tid; k < GPAIRS*HH*GFW; k += 128) sfeat[k] = make_float2(0.f, 0.f);
    for (int k = tid; k < PH*PH; k += 128) srm[k] = 0.f;
    __syncthreads();
    for (int k = tid; k < NPIX; k += 128) {
        int y = k / OH, x = k - y*OH;
        srm[(y+2)*PH + (x+2)] = g_rm[(i*NS + s)*NPIX + k];
    }

    const float* fbase = feat + (((size_t)i*NS + s)*NC + cg*32)*HW;

    #pragma unroll 1
    for (int st = 0; st < 4; st++) {
        __syncthreads();
        for (int k = tid; k < GPAIRS*HW; k += 128) {
            int p = k / HW, q = k - p*HW;
            int u = q / HH, v = q - u*HH;
            int c0 = (st*GPAIRS + p)*2;
            float2 val;
            val.x = fbase[(size_t)c0*HW + q];
            val.y = fbase[(size_t)(c0+1)*HW + q];
            sfeat[p*(HH*GFW) + u*GFW + v] = val;
        }
        __syncthreads();

        float2 acc[4];
        #pragma unroll
        for (int kx = 0; kx < 4; kx++) acc[kx] = make_float2(0.f, 0.f);

        const float2* fch = sfeat + pr*(HH*GFW);
        #pragma unroll 1
        for (int u = 0; u < HH; u++) {
            const float* rmr = srm + (u + 4 - ky)*PH;
            float2 p0 = make_float2(rmr[v0+1], rmr[v0+1]);
            float2 p1 = make_float2(rmr[v0+2], rmr[v0+2]);
            float2 p2 = make_float2(rmr[v0+3], rmr[v0+3]);
            const float2* fr = fch + u*GFW + v0;
            #pragma unroll
            for (int v = 0; v < 3; v++) {
                float rnew = rmr[v0 + v + 4];
                float2 p3 = make_float2(rnew, rnew);
                float2 f = fr[v];
                acc[3] = f2fma(f, p0, acc[3]);
                acc[2] = f2fma(f, p1, acc[2]);
                acc[1] = f2fma(f, p2, acc[1]);
                acc[0] = f2fma(f, p3, acc[0]);
                p0 = p1; p1 = p2; p2 = p3;
            }
        }

        // reduce over the 8 v-segments (low 3 lane bits, groups aligned)
        #pragma unroll
        for (int kx = 0; kx < 4; kx++) {
            #pragma unroll
            for (int o = 4; o > 0; o >>= 1) {
                acc[kx].x += __shfl_down_sync(0xffffffffu, acc[kx].x, o);
                acc[kx].y += __shfl_down_sync(0xffffffffu, acc[kx].y, o);
            }
        }
        if (vseg == 0) {
            int c = cg*32 + (st*GPAIRS + pr)*2;
            size_t base = (size_t)i*WSZ + (size_t)(s*NC + c)*TAPS + ky*4;
            #pragma unroll
            for (int kx = 0; kx < 4; kx++) {
                g_wgpart[base + kx]        = acc[kx].x;
                g_wgpart[base + TAPS + kx] = acc[kx].y;
            }
        }
    }
}

// ---------------- combine grad partials: wg = sum_i part + reg*w; alpha_num; wsq ----------------
__global__ void k_comb(const float* __restrict__ freg, int t) {
    __shared__ float sred[32];
    int idx = blockIdx.x * 256 + threadIdx.x;   // grid covers exactly WSZ
    int s = idx >> 13;                          // / 8192 (256 | 8192 so block is single-s)
    float fr0 = freg[0];
    float regv = fmaxf(fr0*fr0, 1e-6f);
    float w = g_w[idx];
    float wg = g_wgpart[idx] + g_wgpart[WSZ + idx] + g_wgpart[2*WSZ + idx] + regv*w;
    g_wg[idx] = wg;
    float tn = block_reduce_sum(wg*wg, sred);
    if (threadIdx.x == 0) atomicAdd(&g_alpha_num[s], tn);
    __syncthreads();
    float tw = block_reduce_sum(w*w, sred);
    if (threadIdx.x == 0) atomicAdd(&g_wsq[t], tw);
}

// ---------------- alpha_den: (1/3)*sum conv(feat,wg)^2 ; also materialize g_sg ----------------
__global__ void k_den() {
    __shared__ float sred[32];
    int e = blockIdx.x;
    int s = e % NS;
    float sum = 0.f;
    for (int p = threadIdx.x; p < NPIX; p += 256) {
        float v = 0.f;
        #pragma unroll
        for (int ch = 0; ch < CSPLIT; ch++) v += g_spart[ch*(NE*NPIX) + e*NPIX + p];
        g_sg[e*NPIX + p] = v;
        sum += v*v;
    }
    float tot = block_reduce_sum(sum, sred);
    if (threadIdx.x == 0) atomicAdd(&g_alpha_den[s], tot * (1.f/3.f));
}

// ---------------- weight update ----------------
__global__ void k_update(const float* __restrict__ lsl, const float* __restrict__ freg) {
    int idx = blockIdx.x * 256 + threadIdx.x;   // grid sized exactly WSZ
    int s = idx >> 13;                          // / 8192
    float fr0 = freg[0];
    float regv = fmaxf(fr0*fr0, 1e-6f);
    float num = g_alpha_num[s];
    float den = fmaxf(g_alpha_den[s] + regv*num, 1e-8f);
    float alpha = num / den;
    float step = expf(lsl[0]);
    g_w[idx] -= step * alpha * g_wg[idx];
}

// ---------------- scores update: scores -= step*alpha*sg (linear recurrence) ----------------
__global__ void k_supd(const float* __restrict__ lsl, const float* __restrict__ freg) {
    int idx = blockIdx.x * 256 + threadIdx.x;
    if (idx >= NE*NPIX) return;
    int s = (idx / NPIX) % NS;
    float fr0 = freg[0];
    float regv = fmaxf(fr0*fr0, 1e-6f);
    float num = g_alpha_num[s];
    float den = fmaxf(g_alpha_den[s] + regv*num, 1e-8f);
    float alpha = num / den;
    float step = expf(lsl[0]);
    g_scores[idx] -= step * alpha * g_sg[idx];
}

// ---------------- final loss pieces + weight writeback ----------------
__global__ void k_final(float* __restrict__ out) {
    __shared__ float sred[32];
    int b = blockIdx.x;
    if (b < NE) {
        float sum = 0.f;
        for (int p = threadIdx.x; p < NPIX; p += 256) {
            float d = g_scores[b*NPIX + p] - g_label[b*NPIX + p];
            sum += d*d;
        }
        float tot = block_reduce_sum(sum, sred);
        if (threadIdx.x == 0) atomicAdd(&g_loss_data[5], tot * (1.f/3.f));
    } else {
        int j = (b - NE) * 256 + threadIdx.x;   // covers exactly WSZ
        float wv = g_w[j];
        out[j] = wv;
        float tot = block_reduce_sum(wv*wv, sred);
        if (threadIdx.x == 0) atomicAdd(&g_wsq[5], tot);
    }
}

// ---------------- losses writeback ----------------
__global__ void k_last(float* __restrict__ out, const float* __restrict__ freg) {
    float fr0 = freg[0];
    float regv = fmaxf(fr0*fr0, 1e-6f);
    int t = threadIdx.x;
    if (t < 6) out[WSZ + t] = (g_loss_data[t] + regv * g_wsq[t]) * (1.f/(float)NS);
}

// ---------------- launcher ----------------
extern "C" void kernel_launch(void* const* d_in, const int* in_sizes, int n_in,
                              void* d_out, int out_size) {
    const float* w_in = (const float*)d_in[0];
    const float* feat = (const float*)d_in[1];
    const float* bb   = (const float*)d_in[2];
    const float* lsl  = (const float*)d_in[3];
    const float* freg = (const float*)d_in[4];
    float* out = (float*)d_out;
    (void)in_sizes; (void)n_in; (void)out_size;

    k_init<<<1024, 256>>>(w_in, bb);
    k_conv<<<NE*CSPLIT, 96>>>(feat, 0);                     // scores_0 partials (only w-conv!)
    for (int t = 0; t < 5; t++) {
        k_resid<<<(NE*NPIX + 255)/256, 256>>>(t, t == 0);   // rm + loss_data[t] (+zero alphas)
        k_grad<<<NI*NS*16, 128>>>(feat);                    // per-image grad partials
        k_comb<<<WSZ/256, 256>>>(freg, t);                  // wg, alpha_num, wsq[t]
        k_conv<<<NE*CSPLIT, 96>>>(feat, 1);                 // sg partials from wg
        k_den<<<NE, 256>>>();                               // alpha_den + g_sg
        k_update<<<WSZ/256, 256>>>(lsl, freg);              // w -= step*alpha*wg
        k_supd<<<(NE*NPIX + 255)/256, 256>>>(lsl, freg);    // scores -= step*alpha*sg
    }
    k_final<<<NE + WSZ/256, 256>>>(out);                    // loss_data[5], wsq[5], weights out
    k_last<<<1, 32>>>(out, freg);                           // losses out
}

// round 4
// speedup vs baseline: 2.6794x; 1.2404x over previous
#include <cuda_runtime.h>
#include <math.h>

#define NI   3
#define NS   32
#define NC   512
#define HH   22
#define OH   23
#define NPIX (OH*OH)        // 529
#define HW   (HH*HH)        // 484
#define NE   (NI*NS)        // 96
#define TAPS 16
#define WSZ  (NS*NC*TAPS)   // 262144
#define CSPLIT 16
#define PH   27             // padded rm tile stride (floats)
#define SPP  4              // channel-pairs per conv stage
#define SROW 26             // conv smem tile rows
#define SST  28             // conv smem tile row stride (float2)
#define GFW  24             // grad feat smem row stride (float2): 22 + 2 zero pad
#define NPAIR (NC/2)        // 256 pairs per element

// ---------------- scratch (device globals; no runtime allocation) ----------------
__device__ __align__(16) float2 g_feat2[NE*NPAIR*HW];  // pair-interleaved feat (95MB)
__device__ float g_spart[CSPLIT*NE*NPIX]; // conv partials per channel-chunk
__device__ float g_label[NE*NPIX];
__device__ float g_scores[NE*NPIX];       // maintained scores (recurrence)
__device__ float g_sg[NE*NPIX];           // conv(feat, wg) summed
__device__ float g_rm[NE*NPIX];           // residuals_mapped
__device__ float g_w[WSZ];                // working weights
__device__ float g_wg[WSZ];               // weights_grad
__device__ float g_wgpart[NI*WSZ];        // per-image grad partials
__device__ float g_alpha_num[NS];
__device__ float g_alpha_den[NS];
__device__ float g_loss_data[8];
__device__ float g_wsq[8];

// ---------------- helpers ----------------
__device__ __forceinline__ float2 f2fma(float2 a, float2 b, float2 c) {
    float2 d;
    asm("fma.rn.f32x2 %0, %1, %2, %3;"
        : "=l"(reinterpret_cast<unsigned long long&>(d))
        : "l"(reinterpret_cast<unsigned long long&>(a)),
          "l"(reinterpret_cast<unsigned long long&>(b)),
          "l"(reinterpret_cast<unsigned long long&>(c)));
    return d;
}
__device__ __forceinline__ float2 fdup(float v) { return make_float2(v, v); }

__device__ __forceinline__ void cpa16(void* dst, const void* src) {
    unsigned int d = (unsigned int)__cvta_generic_to_shared(dst);
    asm volatile("cp.async.cg.shared.global [%0], [%1], 16;" :: "r"(d), "l"(src));
}
__device__ __forceinline__ void cpa_commit() { asm volatile("cp.async.commit_group;"); }
template<int N> __device__ __forceinline__ void cpa_wait() {
    asm volatile("cp.async.wait_group %0;" :: "n"(N));
}

__device__ __forceinline__ float block_reduce_sum(float v, float* sbuf) {
    int lane = threadIdx.x & 31, wid = threadIdx.x >> 5;
    #pragma unroll
    for (int o = 16; o > 0; o >>= 1) v += __shfl_down_sync(0xffffffffu, v, o);
    if (lane == 0) sbuf[wid] = v;
    __syncthreads();
    int nw = (blockDim.x + 31) >> 5;
    v = (threadIdx.x < nw) ? sbuf[threadIdx.x] : 0.f;
    if (wid == 0) {
        #pragma unroll
        for (int o = 16; o > 0; o >>= 1) v += __shfl_down_sync(0xffffffffu, v, o);
    }
    return v;  // valid on thread 0
}

// ---------------- prep: repack feat into pair-interleaved float2 ----------------
__global__ void k_prep(const float* __restrict__ feat) {
    int idx = blockIdx.x * 256 + threadIdx.x;
    if (idx >= NE*NPAIR*HW) return;
    int p = idx / HW, q = idx - p*HW;          // p = global pair = e*256 + pr
    const float* src = feat + (size_t)(p*2)*HW + q;
    g_feat2[idx] = make_float2(src[0], src[HW]);
}

// ---------------- init: copy weights, build label, zero accumulators ----------------
__global__ void k_init(const float* __restrict__ w_in, const float* __restrict__ bb) {
    int idx = blockIdx.x * 256 + threadIdx.x;
    if (idx < WSZ) g_w[idx] = w_in[idx];
    if (idx < NE*NPIX) {
        int e = idx / NPIX, p = idx - e*NPIX;
        int y = p / OH, x = p - y*OH;
        const float* b = bb + e*4;
        float cc = (b[0] + 0.5f*b[2]) * 0.0625f;   // col center
        float cr = (b[1] + 0.5f*b[3]) * 0.0625f;   // row center
        float dy = (float)y - cr, dx = (float)x - cc;
        g_label[idx] = expf(-0.5f*dy*dy) * expf(-0.5f*dx*dx);
    }
    if (blockIdx.x == 0 && threadIdx.x < 8) {
        g_loss_data[threadIdx.x] = 0.f;
        g_wsq[threadIdx.x] = 0.f;
    }
}

// ---------------- conv: one (e, 32-channel chunk) per block, cp.async double-buffered ----------------
// 96 threads = 24 output tiles (4x across, 6y down; tile 6w x 4t) x 4 pair-lanes.
__global__ __launch_bounds__(96, 4) void k_conv(int use_wg) {
    __shared__ __align__(16) float2 sf[2][SPP*SROW*SST]; // 2 x 4 pairs x 26x28
    __shared__ float2 swt[16][TAPS];                     // 16 pairs x 16 taps
    const float* wts = use_wg ? g_wg : g_w;

    int b = blockIdx.x;
    int e = b % NE;              // i*NS + s
    int chunk = b / NE;          // 0..15
    int s = e % NS;
    int tid = threadIdx.x;
    int pl = tid & 3;            // pair lane within stage
    int t  = tid >> 2;           // tile 0..23
    int tx = t & 3, ty = t >> 2;
    int x0 = tx * 6, y0 = ty * 4;
    int sulim = (ty == 5) ? 6 : 7;   // skip dead row read at bottom tile

    // zero both buffers (pads persist; interiors overwritten by cp.async)
    for (int k = tid; k < 2*SPP*SROW*SST; k += 96)
        ((float2*)sf)[k] = make_float2(0.f, 0.f);
    // load all weights for this chunk (16 pairs x 16 taps)
    for (int k = tid; k < 256; k += 96) {
        int pr = k >> 4, tap = k & 15;
        const float* wp = wts + (s*NC + chunk*32 + pr*2)*TAPS + tap;
        swt[pr][tap] = make_float2(wp[0], wp[TAPS]);
    }
    __syncthreads();

    const float2* fbase = g_feat2 + (size_t)(e*NPAIR + chunk*16)*HW;

    // stage loader: 4 pairs x 22 rows x 11 x 16B
    auto load_stage = [&](int st, float2* dstb) {
        for (int k = tid; k < 968; k += 96) {
            int p = k / 242, rem = k - p*242;
            int u = rem / 11, cc = rem - u*11;
            float2* dst = dstb + p*(SROW*SST) + (u+2)*SST + 2 + cc*2;
            const float2* src = fbase + (st*SPP + p)*HW + u*HH + cc*2;
            cpa16(dst, src);
        }
        cpa_commit();
    };

    float2 acc[4][6];
    #pragma unroll
    for (int r = 0; r < 4; r++)
        #pragma unroll
        for (int j = 0; j < 6; j++) acc[r][j] = make_float2(0.f, 0.f);

    load_stage(0, sf[0]);

    #pragma unroll 1
    for (int st = 0; st < 4; st++) {
        if (st < 3) { load_stage(st+1, sf[(st+1)&1]); cpa_wait<1>(); }
        else        { cpa_wait<0>(); }
        __syncthreads();

        const float2* sfp = sf[st&1] + pl*(SROW*SST);
        // hoist this stage's weights to registers
        float2 wr[16];
        #pragma unroll
        for (int k = 0; k < 16; k++) wr[k] = swt[st*SPP + pl][k];

        #pragma unroll
        for (int su = 0; su < 7; su++) {
            if (su >= sulim) continue;
            const float2* fr = sfp + (y0+su)*SST + x0;
            float2 f[9];
            #pragma unroll
            for (int j = 0; j < 9; j++) f[j] = fr[j];
            #pragma unroll
            for (int ky = 0; ky < 4; ky++) {
                int r = su - ky;
                if (r < 0 || r > 3) continue;
                #pragma unroll
                for (int kx = 0; kx < 4; kx++) {
                    float2 w2 = wr[ky*4 + kx];
                    #pragma unroll
                    for (int j = 0; j < 6; j++)
                        acc[r][j] = f2fma(f[j+kx], w2, acc[r][j]);
                }
            }
        }
        __syncthreads();   // buffer reuse fence (stage st+2 overwrite)
    }

    // sum 2 channels, reduce 4 pair-lanes via shfl
    float* op = g_spart + ((size_t)chunk*NE + e)*NPIX;
    #pragma unroll
    for (int r = 0; r < 4; r++) {
        #pragma unroll
        for (int j = 0; j < 6; j++) {
            float v = acc[r][j].x + acc[r][j].y;
            v += __shfl_down_sync(0xffffffffu, v, 1);
            v += __shfl_down_sync(0xffffffffu, v, 2);
            if (pl == 0) {
                int yy = y0 + r, xx = x0 + j;
                if (yy < OH && xx < OH) op[yy*OH + xx] = v;
            }
        }
    }
}

// ---------------- residuals + loss_data[t], zero per-iter alpha accumulators ----------------
__global__ void k_resid(int t, int from_part) {
    __shared__ float sred[32];
    int idx = blockIdx.x * 256 + threadIdx.x;
    float term = 0.f;
    if (idx < NE*NPIX) {
        float ssum;
        if (from_part) {
            ssum = 0.f;
            #pragma unroll
            for (int ch = 0; ch < CSPLIT; ch++) ssum += g_spart[ch*(NE*NPIX) + idx];
            g_scores[idx] = ssum;
        } else {
            ssum = g_scores[idx];
        }
        float d = ssum - g_label[idx];
        g_rm[idx] = d * (1.f/3.f);
        term = d * d * (1.f/3.f);
    }
    float tot = block_reduce_sum(term, sred);
    if (threadIdx.x == 0) atomicAdd(&g_loss_data[t], tot);
    if (blockIdx.x == 0 && threadIdx.x < NS) {
        g_alpha_num[threadIdx.x] = 0.f;
        g_alpha_den[threadIdx.x] = 0.f;
    }
}

// ---------------- grad: per-image partial of corr(feat, rm) ----------------
// block = (i, s, 32-channel group). 128 threads: [0:1]=vseg(w6) [2:4]=uq [5:6]=pair.
// Each thread owns ALL 16 taps of its channel pair (16 float2 accs).
// 4 stages x 4 pairs; scratch reduction aliases the feat buffer.
__global__ __launch_bounds__(128, 7) void k_grad() {
    __shared__ __align__(16) float2 gf[4*HH*GFW/2*2];   // 4 pairs x 22 x 24 float2 = 16.9KB
    __shared__ float srm[PH*PH];                        // padded rm
    float* scr = (float*)gf;                            // 128x33 scratch alias (4224 floats)

    int b = blockIdx.x;
    int i = b / (NS*16);
    int rem = b - i*(NS*16);
    int s = rem >> 4;
    int cg = rem & 15;           // 32-channel group (16 pairs)
    int tid = threadIdx.x;
    int lane = tid & 31;
    int vseg = tid & 3;
    int uq   = (tid >> 2) & 7;
    int pr   = tid >> 5;         // pair within stage (= warp id)
    int v0 = vseg * 6;
    int u0   = (uq < 6) ? uq*3 : 18 + (uq-6)*2;
    int ulen = (uq < 6) ? 3 : 2;

    for (int k = tid; k < 4*HH*GFW; k += 128) ((float2*)gf)[k] = make_float2(0.f, 0.f);
    for (int k = tid; k < PH*PH; k += 128) srm[k] = 0.f;
    __syncthreads();
    for (int k = tid; k < NPIX; k += 128) {
        int y = k / OH, x = k - y*OH;
        srm[(y+2)*PH + (x+2)] = g_rm[(i*NS + s)*NPIX + k];
    }

    const float2* fbase = g_feat2 + (size_t)((i*NS + s)*NPAIR + cg*16)*HW;

    #pragma unroll 1
    for (int st = 0; st < 4; st++) {
        __syncthreads();  // prior scratch reads / zero done
        // load 4 pairs via float4 (16B), re-zero right-pad cols
        for (int k = tid; k < 968; k += 128) {
            int p = k / 242, r2 = k - p*242;
            int u = r2 / 11, cc = r2 - u*11;
            const float4* src = (const float4*)(fbase + (st*4 + p)*HW + u*HH) + cc;
            float4* dst = (float4*)((float2*)gf + p*(HH*GFW) + u*GFW) + cc;
            *dst = *src;
        }
        for (int k = tid; k < 176; k += 128) {  // 4 pairs x 22 rows x 2 pad cols
            int p = k / 44, r2 = k - p*44;
            int u = r2 >> 1, c = HH + (r2 & 1);
            ((float2*)gf)[p*(HH*GFW) + u*GFW + c] = make_float2(0.f, 0.f);
        }
        __syncthreads();

        float2 acc[16];
        #pragma unroll
        for (int k = 0; k < 16; k++) acc[k] = make_float2(0.f, 0.f);

        const float2* fch = (float2*)gf + pr*(HH*GFW);
        #pragma unroll 1
        for (int uu = 0; uu < ulen; uu++) {
            int u = u0 + uu;
            const float* r0p = srm + (u+4)*PH + v0;      // ky=0
            const float* r1p = r0p - PH;
            const float* r2p = r1p - PH;
            const float* r3p = r2p - PH;
            float w00=r0p[1], w01=r0p[2], w02=r0p[3];
            float w10=r1p[1], w11=r1p[2], w12=r1p[3];
            float w20=r2p[1], w21=r2p[2], w22=r2p[3];
            float w30=r3p[1], w31=r3p[2], w32=r3p[3];
            const float2* fr = fch + u*GFW + v0;
            #pragma unroll
            for (int v = 0; v < 6; v++) {
                float2 f = fr[v];
                float rn0 = r0p[v+4];
                acc[3]  = f2fma(f, fdup(w00), acc[3]);
                acc[2]  = f2fma(f, fdup(w01), acc[2]);
                acc[1]  = f2fma(f, fdup(w02), acc[1]);
                acc[0]  = f2fma(f, fdup(rn0), acc[0]);
                w00=w01; w01=w02; w02=rn0;
                float rn1 = r1p[v+4];
                acc[7]  = f2fma(f, fdup(w10), acc[7]);
                acc[6]  = f2fma(f, fdup(w11), acc[6]);
                acc[5]  = f2fma(f, fdup(w12), acc[5]);
                acc[4]  = f2fma(f, fdup(rn1), acc[4]);
                w10=w11; w11=w12; w12=rn1;
                float rn2 = r2p[v+4];
                acc[11] = f2fma(f, fdup(w20), acc[11]);
                acc[10] = f2fma(f, fdup(w21), acc[10]);
                acc[9]  = f2fma(f, fdup(w22), acc[9]);
                acc[8]  = f2fma(f, fdup(rn2), acc[8]);
                w20=w21; w21=w22; w22=rn2;
                float rn3 = r3p[v+4];
                acc[15] = f2fma(f, fdup(w30), acc[15]);
                acc[14] = f2fma(f, fdup(w31), acc[14]);
                acc[13] = f2fma(f, fdup(w32), acc[13]);
                acc[12] = f2fma(f, fdup(rn3), acc[12]);
                w30=w31; w31=w32; w32=rn3;
            }
        }

        __syncthreads();   // compute done before scratch overwrites gf
        #pragma unroll
        for (int k = 0; k < 16; k++) {
            scr[(pr*32 + k)*33 + lane]      = acc[k].x;
            scr[(pr*32 + 16 + k)*33 + lane] = acc[k].y;
        }
        __syncthreads();
        {   // reduce: thread tid owns output o = tid (sum of 32 partials)
            float sum = 0.f;
            #pragma unroll
            for (int p = 0; p < 32; p++) sum += scr[tid*33 + p];
            int pro = tid >> 5, half = (tid >> 4) & 1, tap = tid & 15;
            int c = cg*32 + (st*4 + pro)*2 + half;
            g_wgpart[(size_t)i*WSZ + (s*NC + c)*TAPS + tap] = sum;
        }
    }
}

// ---------------- combine grad partials: wg = sum_i part + reg*w; alpha_num; wsq ----------------
__global__ void k_comb(const float* __restrict__ freg, int t) {
    __shared__ float sred[32];
    int idx = blockIdx.x * 256 + threadIdx.x;   // grid covers exactly WSZ
    int s = idx >> 13;                          // / 8192
    float fr0 = freg[0];
    float regv = fmaxf(fr0*fr0, 1e-6f);
    float w = g_w[idx];
    float wg = g_wgpart[idx] + g_wgpart[WSZ + idx] + g_wgpart[2*WSZ + idx] + regv*w;
    g_wg[idx] = wg;
    float tn = block_reduce_sum(wg*wg, sred);
    if (threadIdx.x == 0) atomicAdd(&g_alpha_num[s], tn);
    __syncthreads();
    float tw = block_reduce_sum(w*w, sred);
    if (threadIdx.x == 0) atomicAdd(&g_wsq[t], tw);
}

// ---------------- alpha_den: (1/3)*sum conv(feat,wg)^2 ; also materialize g_sg ----------------
__global__ void k_den() {
    __shared__ float sred[32];
    int e = blockIdx.x;
    int s = e % NS;
    float sum = 0.f;
    for (int p = threadIdx.x; p < NPIX; p += 256) {
        float v = 0.f;
        #pragma unroll
        for (int ch = 0; ch < CSPLIT; ch++) v += g_spart[ch*(NE*NPIX) + e*NPIX + p];
        g_sg[e*NPIX + p] = v;
        sum += v*v;
    }
    float tot = block_reduce_sum(sum, sred);
    if (threadIdx.x == 0) atomicAdd(&g_alpha_den[s], tot * (1.f/3.f));
}

// ---------------- merged update: weights and scores ----------------
__global__ void k_upd(const float* __restrict__ lsl, const float* __restrict__ freg) {
    int idx = blockIdx.x * 256 + threadIdx.x;
    float fr0 = freg[0];
    float regv = fmaxf(fr0*fr0, 1e-6f);
    float step = expf(lsl[0]);
    if (idx < WSZ) {
        int s = idx >> 13;
        float num = g_alpha_num[s];
        float den = fmaxf(g_alpha_den[s] + regv*num, 1e-8f);
        g_w[idx] -= step * (num/den) * g_wg[idx];
    } else {
        int j = idx - WSZ;
        if (j < NE*NPIX) {
            int s = (j / NPIX) % NS;
            float num = g_alpha_num[s];
            float den = fmaxf(g_alpha_den[s] + regv*num, 1e-8f);
            g_scores[j] -= step * (num/den) * g_sg[j];
        }
    }
}

// ---------------- final loss pieces + weight writeback ----------------
__global__ void k_final(float* __restrict__ out) {
    __shared__ float sred[32];
    int b = blockIdx.x;
    if (b < NE) {
        float sum = 0.f;
        for (int p = threadIdx.x; p < NPIX; p += 256) {
            float d = g_scores[b*NPIX + p] - g_label[b*NPIX + p];
            sum += d*d;
        }
        float tot = block_reduce_sum(sum, sred);
        if (threadIdx.x == 0) atomicAdd(&g_loss_data[5], tot * (1.f/3.f));
    } else {
        int j = (b - NE) * 256 + threadIdx.x;   // covers exactly WSZ
        float wv = g_w[j];
        out[j] = wv;
        float tot = block_reduce_sum(wv*wv, sred);
        if (threadIdx.x == 0) atomicAdd(&g_wsq[5], tot);
    }
}

// ---------------- losses writeback ----------------
__global__ void k_last(float* __restrict__ out, const float* __restrict__ freg) {
    float fr0 = freg[0];
    float regv = fmaxf(fr0*fr0, 1e-6f);
    int t = threadIdx.x;
    if (t < 6) out[WSZ + t] = (g_loss_data[t] + regv * g_wsq[t]) * (1.f/(float)NS);
}

// ---------------- launcher ----------------
extern "C" void kernel_launch(void* const* d_in, const int* in_sizes, int n_in,
                              void* d_out, int out_size) {
    const float* w_in = (const float*)d_in[0];
    const float* feat = (const float*)d_in[1];
    const float* bb   = (const float*)d_in[2];
    const float* lsl  = (const float*)d_in[3];
    const float* freg = (const float*)d_in[4];
    float* out = (float*)d_out;
    (void)in_sizes; (void)n_in; (void)out_size;

    k_init<<<1024, 256>>>(w_in, bb);
    k_prep<<<(NE*NPAIR*HW + 255)/256, 256>>>(feat);
    k_conv<<<NE*CSPLIT, 96>>>(0);                           // scores_0 partials
    for (int t = 0; t < 5; t++) {
        k_resid<<<(NE*NPIX + 255)/256, 256>>>(t, t == 0);   // rm + loss_data[t]
        k_grad<<<NI*NS*16, 128>>>();                        // per-image grad partials
        k_comb<<<WSZ/256, 256>>>(freg, t);                  // wg, alpha_num, wsq[t]
        k_conv<<<NE*CSPLIT, 96>>>(1);                       // sg partials from wg
        k_den<<<NE, 256>>>();                               // alpha_den + g_sg
        k_upd<<<(WSZ + NE*NPIX + 255)/256, 256>>>(lsl, freg); // w and scores update
    }
    k_final<<<NE + WSZ/256, 256>>>(out);                    // loss_data[5], wsq[5], weights out
    k_last<<<1, 32>>>(out, freg);                           // losses out
}